// round 1
// baseline (speedup 1.0000x reference)
#include <cuda_runtime.h>
#include <cstdint>

// q @ k^T / sqrt(8) + 1, softmax, JAX threefry dropout(p=0.3, key 42), @ v
// Shapes: B=256, H=32, S=16, D=64.  BH = 8192 heads, one block per head.

#define NUM_BH 8192
#define ATT_SCALE 0.35355339059327373f  // 1/sqrt(8)

// threefry2x32 with key (0, 42), 20 rounds. Returns both output words.
__device__ __forceinline__ void threefry2x32_k0_42(uint32_t x0, uint32_t x1,
                                                   uint32_t& o0, uint32_t& o1) {
    const uint32_t ks0 = 0u;
    const uint32_t ks1 = 42u;
    const uint32_t ks2 = 0x1BD11BDAu ^ 0u ^ 42u;
    x0 += ks0;
    x1 += ks1;
#define TF_ROUND(r) { x0 += x1; x1 = __funnelshift_l(x1, x1, (r)); x1 ^= x0; }
    TF_ROUND(13) TF_ROUND(15) TF_ROUND(26) TF_ROUND(6)
    x0 += ks1; x1 += ks2 + 1u;
    TF_ROUND(17) TF_ROUND(29) TF_ROUND(16) TF_ROUND(24)
    x0 += ks2; x1 += ks0 + 2u;
    TF_ROUND(13) TF_ROUND(15) TF_ROUND(26) TF_ROUND(6)
    x0 += ks0; x1 += ks1 + 3u;
    TF_ROUND(17) TF_ROUND(29) TF_ROUND(16) TF_ROUND(24)
    x0 += ks1; x1 += ks2 + 4u;
    TF_ROUND(13) TF_ROUND(15) TF_ROUND(26) TF_ROUND(6)
    x0 += ks2; x1 += ks0 + 5u;
#undef TF_ROUND
    o0 = x0;
    o1 = x1;
}

__global__ __launch_bounds__(256) void attn_dropout_kernel(
    const float* __restrict__ q,
    const float* __restrict__ k,
    const float* __restrict__ v,
    float* __restrict__ out)
{
    __shared__ float Qs[16 * 64];
    __shared__ float Ks[16 * 65];   // padded: bank(t*65+d) = (t+d)%32, conflict-free over t
    __shared__ float Vs[16 * 64];   // unpadded: float4 reads in PV phase
    __shared__ float Ps[16 * 16];

    const int bh  = blockIdx.x;
    const int tid = threadIdx.x;

    const float* qb = q + (size_t)bh * 1024;
    const float* kb = k + (size_t)bh * 1024;
    const float* vb = v + (size_t)bh * 1024;

    // Stage tiles (coalesced: 256 threads x 4 scalar loads each)
    #pragma unroll
    for (int i = tid; i < 1024; i += 256) {
        Qs[i] = qb[i];
        int r = i >> 6, c = i & 63;
        Ks[r * 65 + c] = kb[i];
        Vs[i] = vb[i];
    }
    __syncthreads();

    // ---- Scores: thread (s, t) computes one dot product over d ----
    const int s = tid >> 4;
    const int t = tid & 15;
    const float* qrow = &Qs[s * 64];
    const float* krow = &Ks[t * 65];
    float acc = 0.0f;
    #pragma unroll
    for (int d = 0; d < 64; ++d)
        acc = fmaf(qrow[d], krow[d], acc);
    float sc = acc * ATT_SCALE + 1.0f;   // additive all-ones mask

    // ---- Softmax over t within 16-lane groups ----
    float m = sc;
    #pragma unroll
    for (int o = 8; o; o >>= 1)
        m = fmaxf(m, __shfl_xor_sync(0xffffffffu, m, o, 16));
    float e = expf(sc - m);
    float ssum = e;
    #pragma unroll
    for (int o = 8; o; o >>= 1)
        ssum += __shfl_xor_sync(0xffffffffu, ssum, o, 16);
    float p = e / ssum;

    // ---- Dropout: JAX partitionable threefry. Element flat index (u64):
    //      hi = 0 (size = 2^21 < 2^32), lo = bh*256 + s*16 + t.
    //      bits = out0 ^ out1; u = bitcast(bits>>9 | 1.0f) - 1.0f; keep = u < 0.7f
    {
        uint32_t idx = (uint32_t)bh * 256u + (uint32_t)tid;
        uint32_t b0, b1;
        threefry2x32_k0_42(0u, idx, b0, b1);
        uint32_t bits = b0 ^ b1;
        float u = __uint_as_float((bits >> 9) | 0x3f800000u) - 1.0f;
        p = (u < 0.7f) ? (p / 0.7f) : 0.0f;
    }

    Ps[s * 16 + t] = p;
    __syncthreads();

    // ---- O = P @ V: thread (s2, dq) computes 4 outputs via float4 ----
    const int s2 = tid >> 4;
    const int dq = tid & 15;
    float4 o4 = make_float4(0.f, 0.f, 0.f, 0.f);
    #pragma unroll
    for (int tt = 0; tt < 16; ++tt) {
        float pv = Ps[s2 * 16 + tt];                      // broadcast within warp
        float4 vv = *reinterpret_cast<const float4*>(&Vs[tt * 64 + dq * 4]);
        o4.x = fmaf(pv, vv.x, o4.x);
        o4.y = fmaf(pv, vv.y, o4.y);
        o4.z = fmaf(pv, vv.z, o4.z);
        o4.w = fmaf(pv, vv.w, o4.w);
    }
    *reinterpret_cast<float4*>(out + (size_t)bh * 1024 + s2 * 64 + dq * 4) = o4;
}

extern "C" void kernel_launch(void* const* d_in, const int* in_sizes, int n_in,
                              void* d_out, int out_size) {
    const float* q = (const float*)d_in[0];
    const float* k = (const float*)d_in[1];
    const float* v = (const float*)d_in[2];
    float* out = (float*)d_out;
    attn_dropout_kernel<<<NUM_BH, 256>>>(q, k, v, out);
}